// round 1
// baseline (speedup 1.0000x reference)
#include <cuda_runtime.h>
#include <cuda_bf16.h>

// Problem constants
#define Bc 8
#define Tc 16
#define Nc 1024
#define FIN 32
#define FOUT 64
#define Kc 3
#define CC (Tc*FIN)   // 512 columns of the big GEMM

// Scratch (no cudaMalloc allowed)
__device__ float g_xr [(size_t)Bc * Nc * CC];            // [b][j][t*32+f]   16.8 MB
__device__ float g_rhs[(size_t)Bc * Kc * Nc * CC];       // [b][k][i][t*32+f] 50.3 MB

// ---------------------------------------------------------------------------
// Kernel 1: transpose x [b,t,j,f] -> xr [b,j,t*32+f]  (float4 granularity)
// ---------------------------------------------------------------------------
__global__ void k_transpose_x(const float* __restrict__ x) {
    int idx = blockIdx.x * 256 + threadIdx.x;          // float4 index, total 1,048,576
    int f4 = idx & 7;                                  // 8 float4 per f-row of 32
    int j  = (idx >> 3) & 1023;
    int t  = (idx >> 13) & 15;
    int b  = idx >> 17;
    float4 v = ((const float4*)x)[idx];
    size_t dst = ((size_t)(b * Nc + j) * CC + t * FIN) >> 2;   // in float4 units
    ((float4*)g_xr)[dst + f4] = v;
}

// ---------------------------------------------------------------------------
// Kernel 2: per (b,k) SGEMM:  rhs[b,k,i,c] = sum_j (cheb[k,i,j]*sa[b,i,j]) * xr[b,j,c]
// 128x128 tile, BK=16, 256 threads, 8x8 per-thread micro-tile.
// ---------------------------------------------------------------------------
#define BM 128
#define BN 128
#define BK 16

__global__ __launch_bounds__(256, 2)
void k_gemm_att(const float* __restrict__ cheb, const float* __restrict__ sa) {
    const int bk = blockIdx.z;               // b*3+k
    const int b  = bk / 3;
    const int k  = bk % 3;
    const int tile_i = blockIdx.y * BM;
    const int tile_c = blockIdx.x * BN;

    const float* __restrict__ Ach = cheb + (size_t)k * Nc * Nc;
    const float* __restrict__ Asa = sa   + (size_t)b * Nc * Nc;
    const float* __restrict__ Bx  = g_xr + (size_t)b * Nc * CC;
    float* __restrict__ C         = g_rhs + (size_t)bk * Nc * CC;

    __shared__ float As[BK][BM];   // transposed A tile: As[kk][i]
    __shared__ float Bs[BK][BN];

    const int tid = threadIdx.x;
    const int tx = tid & 15;       // 16 cols of threads
    const int ty = tid >> 4;       // 16 rows of threads

    float acc[8][8];
    #pragma unroll
    for (int i = 0; i < 8; i++)
        #pragma unroll
        for (int j = 0; j < 8; j++) acc[i][j] = 0.f;

    for (int j0 = 0; j0 < Nc; j0 += BK) {
        // --- load A tile (128 rows x 16 cols), fuse cheb*sa; 512 float4 total
        #pragma unroll
        for (int e = 0; e < 2; e++) {
            int li  = tid * 2 + e;              // 0..511
            int row = li >> 2;                  // 0..127
            int c4  = (li & 3) << 2;            // 0,4,8,12
            size_t g = (size_t)(tile_i + row) * Nc + j0 + c4;
            float4 ch = *(const float4*)(Ach + g);
            float4 s  = *(const float4*)(Asa + g);
            As[c4 + 0][row] = ch.x * s.x;
            As[c4 + 1][row] = ch.y * s.y;
            As[c4 + 2][row] = ch.z * s.z;
            As[c4 + 3][row] = ch.w * s.w;
        }
        // --- load B tile (16 rows x 128 cols); 512 float4 total
        #pragma unroll
        for (int e = 0; e < 2; e++) {
            int li  = tid * 2 + e;
            int row = li >> 5;                  // 0..15
            int c4  = (li & 31) << 2;           // 0..124
            size_t g = (size_t)(j0 + row) * CC + tile_c + c4;
            *(float4*)(&Bs[row][c4]) = *(const float4*)(Bx + g);
        }
        __syncthreads();

        #pragma unroll
        for (int kk = 0; kk < BK; kk++) {
            float a[8], bb[8];
            *(float4*)(a)     = *(const float4*)(&As[kk][ty * 8]);
            *(float4*)(a + 4) = *(const float4*)(&As[kk][ty * 8 + 4]);
            *(float4*)(bb)     = *(const float4*)(&Bs[kk][tx * 8]);
            *(float4*)(bb + 4) = *(const float4*)(&Bs[kk][tx * 8 + 4]);
            #pragma unroll
            for (int i = 0; i < 8; i++)
                #pragma unroll
                for (int j = 0; j < 8; j++)
                    acc[i][j] += a[i] * bb[j];
        }
        __syncthreads();
    }

    // --- store 8x8 micro-tile
    #pragma unroll
    for (int i = 0; i < 8; i++) {
        size_t row = (size_t)(tile_i + ty * 8 + i);
        float* crow = C + row * CC + tile_c + tx * 8;
        float4 v0 = make_float4(acc[i][0], acc[i][1], acc[i][2], acc[i][3]);
        float4 v1 = make_float4(acc[i][4], acc[i][5], acc[i][6], acc[i][7]);
        *(float4*)(crow)     = v0;
        *(float4*)(crow + 4) = v1;
    }
}

// ---------------------------------------------------------------------------
// Kernel 3: out[b,t,i,o] = relu( sum_{k,f} rhs[b,k,i,t*32+f] * Theta[k,f,o] )
// One block per (b,i): 16 t x 64 o = 1024 outputs, 256 threads.
// ---------------------------------------------------------------------------
__global__ __launch_bounds__(256)
void k_proj(const float* __restrict__ Theta, float* __restrict__ out) {
    __shared__ float Th[96][FOUT];    // m = k*32+f  -> 24 KB
    __shared__ float rv[Tc][96];      // per-t vector over m -> 6 KB

    const int blk = blockIdx.x;        // b*1024 + i
    const int b = blk >> 10;
    const int i = blk & 1023;
    const int tid = threadIdx.x;

    // Theta [k][f][o] is already flat [96][64]
    #pragma unroll
    for (int idx = tid; idx < 96 * FOUT; idx += 256)
        ((float*)Th)[idx] = Theta[idx];

    #pragma unroll
    for (int k = 0; k < Kc; k++) {
        const float* src = g_rhs + ((size_t)(b * Kc + k) * Nc + i) * CC;
        #pragma unroll
        for (int idx = tid; idx < CC; idx += 256) {
            int t = idx >> 5, f = idx & 31;
            rv[t][k * FIN + f] = src[idx];
        }
    }
    __syncthreads();

    #pragma unroll
    for (int e = 0; e < 4; e++) {
        int oidx = tid + e * 256;      // 0..1023
        int t = oidx >> 6;
        int o = oidx & 63;
        float s = 0.f;
        #pragma unroll
        for (int m = 0; m < 96; m++)
            s = fmaf(rv[t][m], Th[m][o], s);
        out[(((size_t)b * Tc + t) * Nc + i) * FOUT + o] = fmaxf(s, 0.f);
    }
}

// ---------------------------------------------------------------------------
extern "C" void kernel_launch(void* const* d_in, const int* in_sizes, int n_in,
                              void* d_out, int out_size) {
    const float* x     = (const float*)d_in[0];
    const float* sa    = (const float*)d_in[1];
    const float* cheb  = (const float*)d_in[2];
    const float* Theta = (const float*)d_in[3];
    float* out = (float*)d_out;

    // 1) transpose x -> g_xr
    k_transpose_x<<<(Bc * Tc * Nc * FIN / 4) / 256, 256>>>(x);

    // 2) 24 fused (cheb*sa) GEMMs -> g_rhs
    dim3 grid(CC / BN, Nc / BM, Bc * Kc);   // (4, 8, 24)
    k_gemm_att<<<grid, 256>>>(cheb, sa);

    // 3) projection + relu -> out
    k_proj<<<Bc * Nc, 256>>>(Theta, out);
}

// round 3
// speedup vs baseline: 2.6899x; 2.6899x over previous
#include <cuda_runtime.h>
#include <cuda_bf16.h>
#include <cstdint>

// ---------------- problem constants ----------------
#define Bc 8
#define Tc 16
#define Nn 1024
#define FIN 32
#define FOUT 64
#define Kc 3
#define CC 512            // T*F_in columns of the big GEMM

// ---------------- scratch (no cudaMalloc allowed) ----------------
__device__ __nv_bfloat16 g_xh[(size_t)Bc * CC * Nn];   // x transposed [b][c][j], hi bf16 (8 MB)
__device__ __nv_bfloat16 g_xl[(size_t)Bc * CC * Nn];   // lo bf16                        (8 MB)
__device__ float g_rhs[(size_t)Bc * Kc * Nn * CC];     // [b][k][i][c]                   (50 MB)

// ---------------- helpers ----------------
__device__ __forceinline__ uint32_t smem_u32(const void* p) {
    uint32_t a;
    asm("{ .reg .u64 t; cvta.to.shared.u64 t, %1; cvt.u32.u64 %0, t; }" : "=r"(a) : "l"(p));
    return a;
}

// bf16 hi/lo split of two floats, packed as bf16x2 words
__device__ __forceinline__ void split2(float a, float b, uint32_t& hi, uint32_t& lo) {
    __nv_bfloat16 ha = __float2bfloat16_rn(a);
    __nv_bfloat16 hb = __float2bfloat16_rn(b);
    __nv_bfloat16 la = __float2bfloat16_rn(a - __bfloat162float(ha));
    __nv_bfloat16 lb = __float2bfloat16_rn(b - __bfloat162float(hb));
    hi = (uint32_t)__bfloat16_as_ushort(ha) | ((uint32_t)__bfloat16_as_ushort(hb) << 16);
    lo = (uint32_t)__bfloat16_as_ushort(la) | ((uint32_t)__bfloat16_as_ushort(lb) << 16);
}

__device__ __forceinline__ void mma16816(float* d, const uint32_t* a, uint32_t b0, uint32_t b1) {
    asm volatile(
        "mma.sync.aligned.m16n8k16.row.col.f32.bf16.bf16.f32 "
        "{%0,%1,%2,%3}, {%4,%5,%6,%7}, {%8,%9}, {%0,%1,%2,%3};"
        : "+f"(d[0]), "+f"(d[1]), "+f"(d[2]), "+f"(d[3])
        : "r"(a[0]), "r"(a[1]), "r"(a[2]), "r"(a[3]), "r"(b0), "r"(b1));
}

#define LDMATRIX_X4(r, addr) \
    asm volatile("ldmatrix.sync.aligned.m8n8.x4.shared.b16 {%0,%1,%2,%3}, [%4];" \
        : "=r"((r)[0]), "=r"((r)[1]), "=r"((r)[2]), "=r"((r)[3]) : "r"(addr))

#define CP_ASYNC16(dst_u32, src_ptr) \
    asm volatile("cp.async.cg.shared.global [%0], [%1], 16;" :: "r"(dst_u32), "l"(src_ptr))
#define CP_ASYNC_COMMIT() asm volatile("cp.async.commit_group;" ::: "memory")
#define CP_ASYNC_WAIT0()  asm volatile("cp.async.wait_group 0;" ::: "memory")

// ---------------------------------------------------------------------------
// Kernel 1: x [b,t,j,f] -> xT hi/lo bf16 [b, c=t*32+f, j]
// ---------------------------------------------------------------------------
__global__ __launch_bounds__(256)
void k_prep_x(const float* __restrict__ x) {
    __shared__ float tile[128][33];
    const int blk = blockIdx.x;            // 8 jchunks * 16 t * 8 b = 1024
    const int jc = blk & 7;
    const int t  = (blk >> 3) & 15;
    const int b  = blk >> 7;
    const int j0 = jc * 128;
    const int tid = threadIdx.x;

    const float* src = x + (((size_t)b * Tc + t) * Nn + j0) * FIN;
    #pragma unroll
    for (int e = 0; e < 4; e++) {
        int li = e * 256 + tid;            // 1024 float4 (128 j-rows x 8 f4)
        int row = li >> 3, q = li & 7;
        float4 v = ((const float4*)src)[li];
        tile[row][q * 4 + 0] = v.x;
        tile[row][q * 4 + 1] = v.y;
        tile[row][q * 4 + 2] = v.z;
        tile[row][q * 4 + 3] = v.w;
    }
    __syncthreads();

    #pragma unroll
    for (int e = 0; e < 8; e++) {
        int li = e * 256 + tid;            // 2048 bf16x2 (32 f x 64 j-pairs)
        int f = li >> 6, jp = li & 63;
        int jj = jp * 2;
        uint32_t hi, lo;
        split2(tile[jj][f], tile[jj + 1][f], hi, lo);
        size_t off = ((size_t)b * CC + t * FIN + f) * Nn + j0 + jj;
        *(uint32_t*)((char*)g_xh + off * 2) = hi;
        *(uint32_t*)((char*)g_xl + off * 2) = lo;
    }
}

// ---------------------------------------------------------------------------
// Kernel 2: mma.sync GEMM with fused A = cheb*sa, bf16 hi/lo split (3 terms)
// CTA: M=128 (i) x N=256 (c), K=1024 (j), BK=32, double-buffered smem.
// 512 threads, 16 warps in 2(M) x 8(N); warp tile 64x32; m16n8k16 HMMA.
// ---------------------------------------------------------------------------
#define BK 32
#define NSTG 32                         // 1024 / 32
#define AROW 80                         // 32 bf16 padded to 40 (80 bytes)
#define OFF_AH 0
#define OFF_AL 10240
#define OFF_BH 20480
#define OFF_BL 40960
#define STAGE_SZ 61440
#define GEMM_SMEM (2 * STAGE_SZ)        // 120 KB

struct AStage { float4 c[2], s[2]; };

__device__ __forceinline__ void ldg_A(AStage& st, const float* __restrict__ Ach,
                                      const float* __restrict__ Asa, int j0, int tid) {
    #pragma unroll
    for (int e = 0; e < 2; e++) {
        int li = tid + e * 512;            // 1024 float4
        int row = li >> 3, q = li & 7;     // 128 rows x 8 quads
        size_t g = (size_t)row * Nn + j0 + q * 4;
        st.c[e] = *(const float4*)(Ach + g);
        st.s[e] = *(const float4*)(Asa + g);
    }
}

__device__ __forceinline__ void sts_A(const AStage& st, char* sbase, int tid) {
    #pragma unroll
    for (int e = 0; e < 2; e++) {
        int li = tid + e * 512;
        int row = li >> 3, q = li & 7;
        float p0 = st.c[e].x * st.s[e].x, p1 = st.c[e].y * st.s[e].y;
        float p2 = st.c[e].z * st.s[e].z, p3 = st.c[e].w * st.s[e].w;
        uint32_t hA, lA, hB, lB;
        split2(p0, p1, hA, lA);
        split2(p2, p3, hB, lB);
        *(uint2*)(sbase + OFF_AH + row * AROW + q * 8) = make_uint2(hA, hB);
        *(uint2*)(sbase + OFF_AL + row * AROW + q * 8) = make_uint2(lA, lB);
    }
}

__device__ __forceinline__ void cpasync_B(uint32_t sstage, const __nv_bfloat16* __restrict__ Bh,
                                          const __nv_bfloat16* __restrict__ Bl, int j0, int tid) {
    #pragma unroll
    for (int e = 0; e < 2; e++) {
        int li = tid + e * 512;            // 1024 chunks of 16B per half
        int n = li >> 2, q = li & 3;       // 256 rows x 4 x 16B
        const char* srcH = (const char*)(Bh + (size_t)n * Nn + j0) + q * 16;
        const char* srcL = (const char*)(Bl + (size_t)n * Nn + j0) + q * 16;
        CP_ASYNC16(sstage + OFF_BH + n * AROW + q * 16, srcH);
        CP_ASYNC16(sstage + OFF_BL + n * AROW + q * 16, srcL);
    }
}

__global__ __launch_bounds__(512, 1)
void k_gemm_mma(const float* __restrict__ cheb, const float* __restrict__ sa) {
    extern __shared__ char smem[];
    const uint32_t sb = smem_u32(smem);
    const int tid = threadIdx.x;
    const int lane = tid & 31, wid = tid >> 5;
    const int wm = wid >> 3, wn = wid & 7;          // warp grid 2 x 8

    const int tile_c = blockIdx.x * 256;
    const int tile_i = blockIdx.y * 128;
    const int bk = blockIdx.z;
    const int b = bk / 3, kdeg = bk % 3;

    const float* Ach = cheb + (size_t)kdeg * Nn * Nn + (size_t)tile_i * Nn;
    const float* Asa = sa   + (size_t)b    * Nn * Nn + (size_t)tile_i * Nn;
    const __nv_bfloat16* Bh = g_xh + ((size_t)b * CC + tile_c) * Nn;
    const __nv_bfloat16* Bl = g_xl + ((size_t)b * CC + tile_c) * Nn;

    float acc[4][4][4];
    #pragma unroll
    for (int m = 0; m < 4; m++)
        #pragma unroll
        for (int n = 0; n < 4; n++)
            #pragma unroll
            for (int r = 0; r < 4; r++) acc[m][n][r] = 0.f;

    // prologue: stage 0
    AStage st;
    ldg_A(st, Ach, Asa, 0, tid);
    sts_A(st, smem, tid);
    cpasync_B(sb, Bh, Bl, 0, tid);
    CP_ASYNC_COMMIT();

    const uint32_t arow_off = (wm * 64 + (lane & 15)) * AROW + (lane >> 4) * 16;
    const uint32_t brow = (wn * 32 + (lane >> 2)) * AROW + (lane & 3) * 4;

    #pragma unroll 1
    for (int s = 0; s < NSTG; s++) {
        const int buf = s & 1;
        char* cur = smem + buf * STAGE_SZ;
        char* nxt = smem + (buf ^ 1) * STAGE_SZ;
        const uint32_t sb_cur = sb + buf * STAGE_SZ;
        const uint32_t sb_nxt = sb + (buf ^ 1) * STAGE_SZ;

        if (s + 1 < NSTG) ldg_A(st, Ach, Asa, (s + 1) * BK, tid);

        CP_ASYNC_WAIT0();
        __syncthreads();

        if (s + 1 < NSTG) {
            cpasync_B(sb_nxt, Bh, Bl, (s + 1) * BK, tid);
            CP_ASYNC_COMMIT();
        }

        // ---- MMA on current stage ----
        #pragma unroll
        for (int ks = 0; ks < 2; ks++) {
            uint32_t af[4][4];
            #pragma unroll
            for (int mt = 0; mt < 4; mt++)
                LDMATRIX_X4(af[mt], sb_cur + OFF_AH + arow_off + mt * 16 * AROW + ks * 32);
            #pragma unroll
            for (int nt = 0; nt < 4; nt++) {
                uint32_t bo = brow + nt * 8 * AROW + ks * 32;
                uint32_t b0h = *(const uint32_t*)(cur + OFF_BH + bo);
                uint32_t b1h = *(const uint32_t*)(cur + OFF_BH + bo + 16);
                uint32_t b0l = *(const uint32_t*)(cur + OFF_BL + bo);
                uint32_t b1l = *(const uint32_t*)(cur + OFF_BL + bo + 16);
                #pragma unroll
                for (int mt = 0; mt < 4; mt++) {
                    mma16816(acc[mt][nt], af[mt], b0h, b1h);   // hh
                    mma16816(acc[mt][nt], af[mt], b0l, b1l);   // hl
                }
            }
            #pragma unroll
            for (int mt = 0; mt < 4; mt++)
                LDMATRIX_X4(af[mt], sb_cur + OFF_AL + arow_off + mt * 16 * AROW + ks * 32);
            #pragma unroll
            for (int nt = 0; nt < 4; nt++) {
                uint32_t bo = brow + nt * 8 * AROW + ks * 32;
                uint32_t b0h = *(const uint32_t*)(cur + OFF_BH + bo);
                uint32_t b1h = *(const uint32_t*)(cur + OFF_BH + bo + 16);
                #pragma unroll
                for (int mt = 0; mt < 4; mt++)
                    mma16816(acc[mt][nt], af[mt], b0h, b1h);   // lh
            }
        }

        if (s + 1 < NSTG) sts_A(st, nxt, tid);
    }

    // ---- epilogue ----
    float* Cb = g_rhs + (size_t)bk * Nn * CC;
    #pragma unroll
    for (int mt = 0; mt < 4; mt++) {
        int r0 = tile_i + wm * 64 + mt * 16 + (lane >> 2);
        #pragma unroll
        for (int nt = 0; nt < 4; nt++) {
            int c0 = tile_c + wn * 32 + nt * 8 + (lane & 3) * 2;
            *(float2*)(Cb + (size_t)r0 * CC + c0)       = make_float2(acc[mt][nt][0], acc[mt][nt][1]);
            *(float2*)(Cb + (size_t)(r0 + 8) * CC + c0) = make_float2(acc[mt][nt][2], acc[mt][nt][3]);
        }
    }
}

// ---------------------------------------------------------------------------
// Kernel 3: out[b,t,i,o] = relu( sum_{k,f} rhs[b,k,i,t*32+f] * Theta[k,f,o] )
// 4 i-rows per block; register-blocked 4x4; Theta transposed in smem.
// ---------------------------------------------------------------------------
__global__ __launch_bounds__(256)
void k_proj(const float* __restrict__ Theta, float* __restrict__ out) {
    __shared__ float ThT[64 * 97];      // [o][m], odd pad for conflict-free scalar loads
    __shared__ float rv[4 * 16 * 96];   // [ii][t][m]

    const int blk = blockIdx.x;         // 8 b * 256 i-groups
    const int b = blk >> 8;
    const int i0 = (blk & 255) * 4;
    const int tid = threadIdx.x;

    for (int idx = tid; idx < 96 * 64; idx += 256) {
        int o = idx & 63, m = idx >> 6;
        ThT[o * 97 + m] = Theta[idx];
    }
    #pragma unroll
    for (int ii = 0; ii < 4; ii++)
        #pragma unroll
        for (int k = 0; k < Kc; k++) {
            const float* src = g_rhs + ((size_t)(b * Kc + k) * Nn + i0 + ii) * CC;
            #pragma unroll
            for (int e = 0; e < 2; e++) {
                int idx = tid + e * 256;
                int t = idx >> 5, f = idx & 31;
                rv[(ii * 16 + t) * 96 + k * FIN + f] = src[idx];
            }
        }
    __syncthreads();

    const int og = tid & 15;            // o group (4 o's)
    const int t  = tid >> 4;            // time step
    float acc[4][4];
    #pragma unroll
    for (int p = 0; p < 4; p++)
        #pragma unroll
        for (int q = 0; q < 4; q++) acc[p][q] = 0.f;

    #pragma unroll
    for (int mq = 0; mq < 24; mq++) {
        float4 r4[4];
        #pragma unroll
        for (int p = 0; p < 4; p++)
            r4[p] = *(const float4*)&rv[(p * 16 + t) * 96 + mq * 4];
        float th[4][4];
        #pragma unroll
        for (int q = 0; q < 4; q++) {
            const float* tp = &ThT[(og * 4 + q) * 97 + mq * 4];
            th[q][0] = tp[0]; th[q][1] = tp[1]; th[q][2] = tp[2]; th[q][3] = tp[3];
        }
        #pragma unroll
        for (int p = 0; p < 4; p++)
            #pragma unroll
            for (int q = 0; q < 4; q++) {
                acc[p][q] = fmaf(r4[p].x, th[q][0], acc[p][q]);
                acc[p][q] = fmaf(r4[p].y, th[q][1], acc[p][q]);
                acc[p][q] = fmaf(r4[p].z, th[q][2], acc[p][q]);
                acc[p][q] = fmaf(r4[p].w, th[q][3], acc[p][q]);
            }
    }

    #pragma unroll
    for (int p = 0; p < 4; p++) {
        float4 v = make_float4(fmaxf(acc[p][0], 0.f), fmaxf(acc[p][1], 0.f),
                               fmaxf(acc[p][2], 0.f), fmaxf(acc[p][3], 0.f));
        *(float4*)(out + (((size_t)b * Tc + t) * Nn + i0 + p) * FOUT + og * 4) = v;
    }
}

// ---------------------------------------------------------------------------
extern "C" void kernel_launch(void* const* d_in, const int* in_sizes, int n_in,
                              void* d_out, int out_size) {
    const float* x     = (const float*)d_in[0];
    const float* sa    = (const float*)d_in[1];
    const float* cheb  = (const float*)d_in[2];
    const float* Theta = (const float*)d_in[3];
    float* out = (float*)d_out;

    cudaFuncSetAttribute(k_gemm_mma, cudaFuncAttributeMaxDynamicSharedMemorySize, GEMM_SMEM);

    // 1) transpose + bf16 hi/lo split of x -> g_xh/g_xl [b][c][j]
    k_prep_x<<<1024, 256>>>(x);

    // 2) 24 fused (cheb*sa) GEMMs on tensor cores (mma.sync) -> g_rhs
    dim3 grid(2, 8, Bc * Kc);     // (c tiles, i tiles, b*k)
    k_gemm_mma<<<grid, 512, GEMM_SMEM>>>(cheb, sa);

    // 3) projection + relu -> out
    k_proj<<<Bc * 256, 256>>>(Theta, out);
}